// round 1
// baseline (speedup 1.0000x reference)
#include <cuda_runtime.h>
#include <math.h>

#define TWO_PI_F 6.2831853071795864769f

struct RectCtx {
    float Ax, Ay, Bx, By;
    float ABx, ABy, BCx, BCy;
    float ABAB, BCBC;
};

__device__ __forceinline__ RectCtx make_ctx(const float2* r) {
    RectCtx c;
    c.Ax = r[0].x; c.Ay = r[0].y;
    c.Bx = r[1].x; c.By = r[1].y;
    c.ABx = r[1].x - r[0].x; c.ABy = r[1].y - r[0].y;
    c.BCx = r[2].x - r[1].x; c.BCy = r[2].y - r[1].y;
    c.ABAB = c.ABx * c.ABx + c.ABy * c.ABy;
    c.BCBC = c.BCx * c.BCx + c.BCy * c.BCy;
    return c;
}

// Matches reference is_point_in_rect with epsilon = 0.01 (as called).
// NaN coords -> all comparisons false -> false (same as JAX).
__device__ __forceinline__ bool in_rect(float px, float py, const RectCtx& c, float eps) {
    float AMx = px - c.Ax, AMy = py - c.Ay;
    float BMx = px - c.Bx, BMy = py - c.By;
    float ABAM = c.ABx * AMx + c.ABy * AMy;
    float BCBM = c.BCx * BMx + c.BCy * BMy;
    return (0.0f <= ABAM + eps) && (ABAM <= c.ABAB + eps) &&
           (0.0f <= BCBM + eps) && (BCBM <= c.BCBC + eps);
}

__global__ void obb_iou_kernel(const float* __restrict__ b1,
                               const float* __restrict__ b2,
                               float* __restrict__ out, int n) {
    int i = blockIdx.x * blockDim.x + threadIdx.x;
    if (i >= n) return;

    // ---- load rects (8 floats each, two float4 loads) ----
    float2 r1[4], r2[4];
    {
        const float4* p1 = reinterpret_cast<const float4*>(b1 + (size_t)i * 8);
        const float4* p2 = reinterpret_cast<const float4*>(b2 + (size_t)i * 8);
        float4 a0 = p1[0], a1 = p1[1];
        float4 c0 = p2[0], c1 = p2[1];
        r1[0] = make_float2(a0.x, a0.y); r1[1] = make_float2(a0.z, a0.w);
        r1[2] = make_float2(a1.x, a1.y); r1[3] = make_float2(a1.z, a1.w);
        r2[0] = make_float2(c0.x, c0.y); r2[1] = make_float2(c0.z, c0.w);
        r2[2] = make_float2(c1.x, c1.y); r2[3] = make_float2(c1.z, c1.w);
    }

    // ---- 16 edge-edge line intersections (kept in registers) ----
    float ptx[24], pty[24];
    #pragma unroll
    for (int e1 = 0; e1 < 4; e1++) {
        float2 P1 = r1[e1], P2 = r1[(e1 + 1) & 3];
        float a    = P1.x * P2.y - P1.y * P2.x;
        float dx12 = P1.x - P2.x, dy12 = P1.y - P2.y;
        #pragma unroll
        for (int e2 = 0; e2 < 4; e2++) {
            float2 P3 = r2[e2], P4 = r2[(e2 + 1) & 3];
            float b    = P3.x * P4.y - P3.y * P4.x;
            float dx34 = P3.x - P4.x, dy34 = P3.y - P4.y;
            float den = dx12 * dy34 - dy12 * dx34;
            // reference: where(|den|<1e-12, +1e-12, den)  (sign NOT preserved)
            if (fabsf(den) < 1e-12f) den = 1e-12f;
            float Px = __fdiv_rn(a * dx34 - dx12 * b, den);
            float Py = __fdiv_rn(a * dy34 - dy12 * b, den);
            ptx[e1 * 4 + e2] = Px;
            pty[e1 * 4 + e2] = Py;
        }
    }
    #pragma unroll
    for (int k = 0; k < 4; k++) { ptx[16 + k] = r1[k].x; pty[16 + k] = r1[k].y; }
    #pragma unroll
    for (int k = 0; k < 4; k++) { ptx[20 + k] = r2[k].x; pty[20 + k] = r2[k].y; }

    // ---- membership mask (eps = 0.01, as in calc_intersection_area) ----
    RectCtx c1 = make_ctx(r1);
    RectCtx c2 = make_ctx(r2);
    const float EPS = 0.01f;
    unsigned mask = 0u;
    #pragma unroll
    for (int k = 0; k < 16; k++)
        if (in_rect(ptx[k], pty[k], c1, EPS) && in_rect(ptx[k], pty[k], c2, EPS))
            mask |= 1u << k;
    #pragma unroll
    for (int k = 0; k < 4; k++)
        if (in_rect(r1[k].x, r1[k].y, c2, EPS)) mask |= 1u << (16 + k);
    #pragma unroll
    for (int k = 0; k < 4; k++)
        if (in_rect(r2[k].x, r2[k].y, c1, EPS)) mask |= 1u << (20 + k);

    // ---- duplicates mask: keep[i] = !any_{j<i}( L1(p_i,p_j) < 0.01 ) ----
    // NaN distance -> comparison false -> not a duplicate (same as JAX).
    unsigned keep = 1u;  // index 0 always kept
    #pragma unroll
    for (int a_ = 1; a_ < 24; a_++) {
        bool dup = false;
        float ax = ptx[a_], ay = pty[a_];
        #pragma unroll
        for (int b_ = 0; b_ < a_; b_++) {
            float d = fabsf(ax - ptx[b_]) + fabsf(ay - pty[b_]);
            dup = dup || (d < 0.01f);
        }
        if (!dup) keep |= 1u << a_;
    }

    unsigned mk = mask & keep;

    // ---- stable top_k(mask_i, 8): masked indices ascending, then unmasked ----
    float kpx[8], kpy[8];
    int   km[8];
    int cnt = 0;
    #pragma unroll
    for (int k = 0; k < 24; k++) {
        if (cnt < 8 && ((mk >> k) & 1u)) {
            kpx[cnt] = ptx[k]; kpy[cnt] = pty[k]; km[cnt] = 1; cnt++;
        }
    }
    #pragma unroll
    for (int k = 0; k < 24; k++) {
        if (cnt < 8 && !((mk >> k) & 1u)) {
            kpx[cnt] = ptx[k]; kpy[cnt] = pty[k]; km[cnt] = 0; cnt++;
        }
    }

    // ---- NaN/Inf -> 0 ----
    #pragma unroll
    for (int t = 0; t < 8; t++) {
        if (!isfinite(kpx[t])) kpx[t] = 0.0f;
        if (!isfinite(kpy[t])) kpy[t] = 0.0f;
    }

    // ---- convex_polygon_area ----
    float ox = kpx[0], oy = kpy[0];  // origin = first selected point
    float ppx[8], ppy[8];
    float sx = 0.0f, sy = 0.0f, sm = 0.0f;
    #pragma unroll
    for (int t = 0; t < 8; t++) {
        float m = (float)km[t];
        float vx = m * kpx[t] + (1.0f - m) * ox;
        float vy = m * kpy[t] + (1.0f - m) * oy;
        ppx[t] = vx; ppy[t] = vy;
        sx += vx * m; sy += vy * m; sm += m;
    }
    float inv = __fdiv_rn(1.0f, sm + 1e-6f);
    float cx = sx * inv, cy = sy * inv;
    // NOTE: reference does sum(pp*m)/(sum(m)+1e-6) — two divides of the two
    // components by the same denominator. Keep exact form:
    cx = __fdiv_rn(sx, sm + 1e-6f);
    cy = __fdiv_rn(sy, sm + 1e-6f);
    (void)inv;

    float ang[8];
    #pragma unroll
    for (int t = 0; t < 8; t++) {
        ppx[t] -= cx; ppy[t] -= cy;
        ang[t] = atan2f(ppx[t], ppy[t]);  // atan2(comp0, comp1), per reference
    }
    float a0 = ang[0];
    #pragma unroll
    for (int t = 0; t < 8; t++) {
        float v = ang[t] - a0;
        if (v < 0.0f) v += TWO_PI_F;
        ang[t] = v;
    }

    // stable ascending insertion sort of indices by angle
    int ord[8] = {0, 1, 2, 3, 4, 5, 6, 7};
    #pragma unroll
    for (int s = 1; s < 8; s++) {
        int key = ord[s];
        float ka = ang[key];
        int j = s - 1;
        while (j >= 0 && ang[ord[j]] > ka) {
            ord[j + 1] = ord[j];
            j--;
        }
        ord[j + 1] = key;
    }

    // fan triangulation: triangles (sp0, sp[i], sp[i+1]) for i=1..6
    float s0x = ppx[ord[0]], s0y = ppy[ord[0]];
    float inter = 0.0f;
    #pragma unroll
    for (int t = 1; t <= 6; t++) {
        float axp = ppx[ord[t]],     ayp = ppy[ord[t]];
        float bxp = ppx[ord[t + 1]], byp = ppy[ord[t + 1]];
        inter += 0.5f * fabsf(s0x * (ayp - byp) + axp * (byp - s0y) + bxp * (s0y - ayp));
    }

    // ---- rectangle areas (reference formula: 2x triangle(0,1,2), no 0.5) ----
    float a1 = fabsf(r1[0].x * (r1[1].y - r1[2].y) +
                     r1[1].x * (r1[2].y - r1[0].y) +
                     r1[2].x * (r1[0].y - r1[1].y));
    float a2 = fabsf(r2[0].x * (r2[1].y - r2[2].y) +
                     r2[1].x * (r2[2].y - r2[0].y) +
                     r2[2].x * (r2[0].y - r2[1].y));

    float uni = a1 + a2 - inter;
    out[i] = __fdiv_rn(inter, uni);
}

extern "C" void kernel_launch(void* const* d_in, const int* in_sizes, int n_in,
                              void* d_out, int out_size) {
    const float* b1 = (const float*)d_in[0];
    const float* b2 = (const float*)d_in[1];
    float* out = (float*)d_out;
    int n = in_sizes[0] / 8;  // [N,4,2] floats
    int threads = 256;
    int blocks = (n + threads - 1) / threads;
    obb_iou_kernel<<<blocks, threads>>>(b1, b2, out, n);
}

// round 2
// speedup vs baseline: 2.1161x; 2.1161x over previous
#include <cuda_runtime.h>
#include <math.h>

struct RectCtx {
    float Ax, Ay, Bx, By;
    float ABx, ABy, BCx, BCy;
    float ABABe, BCBCe;   // ABAB + eps, BCBC + eps (precomputed)
};

#define EPS_IN 0.01f

__device__ __forceinline__ RectCtx make_ctx(const float2* r) {
    RectCtx c;
    c.Ax = r[0].x; c.Ay = r[0].y;
    c.Bx = r[1].x; c.By = r[1].y;
    c.ABx = r[1].x - r[0].x; c.ABy = r[1].y - r[0].y;
    c.BCx = r[2].x - r[1].x; c.BCy = r[2].y - r[1].y;
    c.ABABe = c.ABx * c.ABx + c.ABy * c.ABy + EPS_IN;
    c.BCBCe = c.BCx * c.BCx + c.BCy * c.BCy + EPS_IN;
    return c;
}

// Reference is_point_in_rect with eps=0.01. NaN/Inf coords -> false (IEEE).
__device__ __forceinline__ bool in_rect(float px, float py, const RectCtx& c) {
    float ABAM = c.ABx * (px - c.Ax) + c.ABy * (py - c.Ay);
    float BCBM = c.BCx * (px - c.Bx) + c.BCy * (py - c.By);
    return (ABAM >= -EPS_IN) && (ABAM <= c.ABABe) &&
           (BCBM >= -EPS_IN) && (BCBM <= c.BCBCe);
}

// Diamond pseudo-angle: strictly monotone in atan2(u, v), range [-2, 2].
// Matches reference's ang = atan2(comp0, comp1) ordering exactly.
__device__ __forceinline__ float pseudo_ang(float u, float v) {
    float t = fabsf(u) + fabsf(v);
    float r = (t > 0.0f) ? __fdividef(v, t) : 1.0f;   // t==0 -> key 0 (atan2(0,0)=0)
    return copysignf(1.0f - r, u);
}

__global__ void __launch_bounds__(128)
obb_iou_kernel(const float* __restrict__ b1,
               const float* __restrict__ b2,
               float* __restrict__ out, int n) {
    int i = blockIdx.x * blockDim.x + threadIdx.x;
    if (i >= n) return;

    // ---- load rects (two float4 loads each) ----
    float2 r1[4], r2[4];
    {
        const float4* p1 = reinterpret_cast<const float4*>(b1 + (size_t)i * 8);
        const float4* p2 = reinterpret_cast<const float4*>(b2 + (size_t)i * 8);
        float4 a0 = p1[0], a1 = p1[1];
        float4 c0 = p2[0], c1 = p2[1];
        r1[0] = make_float2(a0.x, a0.y); r1[1] = make_float2(a0.z, a0.w);
        r1[2] = make_float2(a1.x, a1.y); r1[3] = make_float2(a1.z, a1.w);
        r2[0] = make_float2(c0.x, c0.y); r2[1] = make_float2(c0.z, c0.w);
        r2[2] = make_float2(c1.x, c1.y); r2[3] = make_float2(c1.z, c1.w);
    }

    // ---- 16 edge-edge line intersections (fast reciprocal) ----
    float px[24], py[24];
    #pragma unroll
    for (int e1 = 0; e1 < 4; e1++) {
        float2 P1 = r1[e1], P2 = r1[(e1 + 1) & 3];
        float a    = P1.x * P2.y - P1.y * P2.x;
        float dx12 = P1.x - P2.x, dy12 = P1.y - P2.y;
        #pragma unroll
        for (int e2 = 0; e2 < 4; e2++) {
            float2 P3 = r2[e2], P4 = r2[(e2 + 1) & 3];
            float b    = P3.x * P4.y - P3.y * P4.x;
            float dx34 = P3.x - P4.x, dy34 = P3.y - P4.y;
            float den = dx12 * dy34 - dy12 * dx34;
            if (fabsf(den) < 1e-12f) den = 1e-12f;      // reference clamp (sign lost)
            float rden = __fdividef(1.0f, den);
            px[e1 * 4 + e2] = (a * dx34 - dx12 * b) * rden;
            py[e1 * 4 + e2] = (a * dy34 - dy12 * b) * rden;
        }
    }
    #pragma unroll
    for (int k = 0; k < 4; k++) { px[16 + k] = r1[k].x; py[16 + k] = r1[k].y; }
    #pragma unroll
    for (int k = 0; k < 4; k++) { px[20 + k] = r2[k].x; py[20 + k] = r2[k].y; }

    // ---- membership mask (eps = 0.01) ----
    RectCtx c1 = make_ctx(r1);
    RectCtx c2 = make_ctx(r2);
    unsigned mask = 0u;
    #pragma unroll
    for (int k = 0; k < 16; k++)
        if (in_rect(px[k], py[k], c1) && in_rect(px[k], py[k], c2))
            mask |= 1u << k;
    #pragma unroll
    for (int k = 0; k < 4; k++)
        if (in_rect(r1[k].x, r1[k].y, c2)) mask |= 1u << (16 + k);
    #pragma unroll
    for (int k = 0; k < 4; k++)
        if (in_rect(r2[k].x, r2[k].y, c1)) mask |= 1u << (20 + k);

    // ---- duplicates: keep[i] = !any_{j<i}( L1(p_i,p_j) < 0.01 ) ----
    unsigned keep = 1u;
    #pragma unroll
    for (int a_ = 1; a_ < 24; a_++) {
        float ax = px[a_], ay = py[a_];
        float mind = 1e30f;
        #pragma unroll
        for (int b_ = 0; b_ < a_; b_++) {
            float d = fabsf(ax - px[b_]) + fabsf(ay - py[b_]);
            mind = fminf(mind, d);
        }
        // NaN d -> fminf keeps mind -> not duplicate (JAX semantics)
        if (!(mind < 0.01f)) keep |= 1u << a_;
    }

    unsigned mk = mask & keep;

    // ---- stable top_k(8): first 8 masked indices ascending; pads -> slot0 ----
    float kx[8], ky[8];
    kx[0] = px[0]; ky[0] = py[0];     // default if no valid point at all
    int cnt = 0;
    float sx = 0.0f, sy = 0.0f, sm = 0.0f;
    #pragma unroll
    for (int k = 0; k < 24; k++) {
        if (((mk >> k) & 1u) && cnt < 8) {
            kx[cnt] = px[k]; ky[cnt] = py[k];
            sx += px[k]; sy += py[k]; sm += 1.0f;
            cnt++;
        }
    }
    // In the reference, pad slots (mask 0) are replaced by origin = kp[0]
    // inside convex_polygon_area, and contribute 0 to the centroid.
    float f0x = kx[0], f0y = ky[0];
    #pragma unroll
    for (int t = 1; t < 8; t++) {
        if (t >= cnt) { kx[t] = f0x; ky[t] = f0y; }
    }

    // ---- NaN/Inf -> 0 (valid points are always finite; only slot-0-copies
    //      when cnt==0 can be non-finite) ----
    #pragma unroll
    for (int t = 0; t < 8; t++) {
        if (!isfinite(kx[t])) kx[t] = 0.0f;
        if (!isfinite(ky[t])) ky[t] = 0.0f;
    }

    // ---- centroid over valid points only (matches sum(pp*m)/(sum(m)+1e-6)) ----
    float cxx = __fdividef(sx, sm + 1e-6f);
    float cyy = __fdividef(sy, sm + 1e-6f);

    // ---- center + pseudo-angle keys, wrapped to start at slot 0's angle ----
    float w[8];
    #pragma unroll
    for (int t = 0; t < 8; t++) {
        kx[t] -= cxx; ky[t] -= cyy;
        w[t] = pseudo_ang(kx[t], ky[t]);   // monotone substitute for atan2(x0, x1)
    }
    float p0 = w[0];
    #pragma unroll
    for (int t = 0; t < 8; t++) {
        float d = w[t] - p0;
        w[t] = (d < 0.0f) ? d + 4.0f : d;  // wrap by 4 (pseudo-angle period)
    }

    // ---- 8-element Batcher sorting network on (w, kx, ky): registers only ----
    #define CE(A, B) { \
        float wa = w[A], wb = w[B]; bool p_ = wa > wb; \
        w[A] = fminf(wa, wb); w[B] = fmaxf(wa, wb); \
        float tx = kx[A]; kx[A] = p_ ? kx[B] : tx; kx[B] = p_ ? tx : kx[B]; \
        float ty = ky[A]; ky[A] = p_ ? ky[B] : ty; ky[B] = p_ ? ty : ky[B]; }
    CE(0,1) CE(2,3) CE(4,5) CE(6,7)
    CE(0,2) CE(1,3) CE(4,6) CE(5,7)
    CE(1,2) CE(5,6) CE(0,4) CE(3,7)
    CE(1,5) CE(2,6)
    CE(1,4) CE(3,6)
    CE(2,4) CE(3,5)
    CE(3,4)
    #undef CE

    // ---- fan triangulation from sorted vertex 0 ----
    float s0x = kx[0], s0y = ky[0];
    float inter = 0.0f;
    #pragma unroll
    for (int t = 1; t <= 6; t++) {
        float axp = kx[t],     ayp = ky[t];
        float bxp = kx[t + 1], byp = ky[t + 1];
        inter += 0.5f * fabsf(s0x * (ayp - byp) + axp * (byp - s0y) + bxp * (s0y - ayp));
    }

    // ---- rectangle areas (reference formula) ----
    float a1 = fabsf(r1[0].x * (r1[1].y - r1[2].y) +
                     r1[1].x * (r1[2].y - r1[0].y) +
                     r1[2].x * (r1[0].y - r1[1].y));
    float a2 = fabsf(r2[0].x * (r2[1].y - r2[2].y) +
                     r2[1].x * (r2[2].y - r2[0].y) +
                     r2[2].x * (r2[0].y - r2[1].y));

    float uni = a1 + a2 - inter;
    out[i] = __fdividef(inter, uni);
}

extern "C" void kernel_launch(void* const* d_in, const int* in_sizes, int n_in,
                              void* d_out, int out_size) {
    const float* b1 = (const float*)d_in[0];
    const float* b2 = (const float*)d_in[1];
    float* out = (float*)d_out;
    int n = in_sizes[0] / 8;   // [N,4,2] floats
    int threads = 128;
    int blocks = (n + threads - 1) / threads;
    obb_iou_kernel<<<blocks, threads>>>(b1, b2, out, n);
}